// round 10
// baseline (speedup 1.0000x reference)
#include <cuda_runtime.h>
#include <cuda_bf16.h>
#include <cuda_fp16.h>
#include <cuda_fp8.h>
#include <math.h>
#include <stdint.h>

#define N 8192
#define D 128
#define NB 64                 // N / 128
#define NTILES (NB * (NB + 1) / 2)     // 2080
#define K2GRID 304            // persistent: 2 CTAs/SM
#define ENC_NEGINF 0x007FFFFFu
#define NEGINF __int_as_float(0xff800000)

// ---------------- scratch (static __device__, no allocation) ----------------
__device__ unsigned g_rowmax[N];   // encoded-float max_{j!=i} (2*G_ij - sq_j)
__device__ float    g_sq[N];
__device__ int      g_flaglist[N];
__device__ int      g_ticket;
__device__ __align__(16) unsigned char g_x8[N * D];   // fp8 e4m3 copy of x (1 MB)

// ---------------- helpers ----------------
__device__ __forceinline__ uint32_t smem_u32(const void* p) {
    uint32_t a;
    asm("{ .reg .u64 t; cvta.to.shared.u64 t, %1; cvt.u32.u64 %0, t; }" : "=r"(a) : "l"(p));
    return a;
}
__device__ __forceinline__ float softplus_var(const float* __restrict__ phi) {
    float p = *phi;
    return (p > 20.f) ? p : log1pf(expf(p));
}
__device__ __forceinline__ unsigned fenc(float f) {
    unsigned u = __float_as_uint(f);
    return (u & 0x80000000u) ? ~u : (u | 0x80000000u);
}
__device__ __forceinline__ float fdec(unsigned e) {
    return (e & 0x80000000u) ? __uint_as_float(e & 0x7FFFFFFFu)
                             : __uint_as_float(~e);
}

__device__ __forceinline__ void ldsm_x4(uint32_t& r0, uint32_t& r1, uint32_t& r2, uint32_t& r3,
                                        uint32_t addr) {
    asm volatile("ldmatrix.sync.aligned.m8n8.x4.shared.b16 {%0,%1,%2,%3}, [%4];"
                 : "=r"(r0), "=r"(r1), "=r"(r2), "=r"(r3) : "r"(addr));
}
__device__ __forceinline__ void ldsm_x2(uint32_t& r0, uint32_t& r1, uint32_t addr) {
    asm volatile("ldmatrix.sync.aligned.m8n8.x2.shared.b16 {%0,%1}, [%2];"
                 : "=r"(r0), "=r"(r1) : "r"(addr));
}
// fp8 e4m3 mma with f16 accumulators
__device__ __forceinline__ void mma_fp8_h(uint32_t* d, const uint32_t* a, const uint32_t* b) {
    asm volatile(
        "mma.sync.aligned.m16n8k32.row.col.f16.e4m3.e4m3.f16 "
        "{%0,%1}, {%2,%3,%4,%5}, {%6,%7}, {%0,%1};"
        : "+r"(d[0]), "+r"(d[1])
        : "r"(a[0]), "r"(a[1]), "r"(a[2]), "r"(a[3]), "r"(b[0]), "r"(b[1]));
}
__device__ __forceinline__ uint16_t cvt2_e4m3(float hi, float lo) {
    uint16_t r;
    asm("cvt.rn.satfinite.e4m3x2.f32 %0, %1, %2;" : "=h"(r) : "f"(hi), "f"(lo));
    return r;
}
__device__ __forceinline__ void cp16(uint32_t dst, const void* src) {
    asm volatile("cp.async.cg.shared.global [%0], [%1], 16;" :: "r"(dst), "l"(src));
}
#define CP_COMMIT() asm volatile("cp.async.commit_group;" ::: "memory")
#define CP_WAIT0()  asm volatile("cp.async.wait_group 0;" ::: "memory")
#define CP_WAIT1()  asm volatile("cp.async.wait_group 1;" ::: "memory")

// ---------------- K1 lite: g_x8 + g_sq + init only ----------------
__global__ __launch_bounds__(256) void k1_lite(const float* __restrict__ x) {
    int tid = threadIdx.x;
    int gw = blockIdx.x * 8 + (tid >> 5);     // 4096 warps, 2 rows each
    int lane = tid & 31;
    int r0 = gw * 2;

    float4 xs[2];
    #pragma unroll
    for (int rr = 0; rr < 2; rr++) xs[rr] = ((const float4*)x)[(r0 + rr) * 32 + lane];

    #pragma unroll
    for (int rr = 0; rr < 2; rr++) {
        float4 xv = xs[rr];
        uint32_t packed = (uint32_t)cvt2_e4m3(xv.y, xv.x)
                        | ((uint32_t)cvt2_e4m3(xv.w, xv.z) << 16);
        ((uint32_t*)g_x8)[(r0 + rr) * 32 + lane] = packed;

        float s = xv.x * xv.x + xv.y * xv.y + xv.z * xv.z + xv.w * xv.w;
        #pragma unroll
        for (int o = 16; o; o >>= 1) s += __shfl_xor_sync(0xffffffffu, s, o);
        if (lane == 0) g_sq[r0 + rr] = s;
    }
    if (lane < 2) g_rowmax[r0 + lane] = ENC_NEGINF;
    if (gw == 0 && lane == 0) g_ticket = 0;
}

// ---------------- K2: persistent fp8 mma Gram + out-injection + fused tail ----------------
#define ROWB 144
#define TILEB (128 * ROWB)     // 18432 bytes per operand tile

__device__ __forceinline__ void decode_tile(int b, int& bi, int& bj) {
    int i = 0, rem = b;
    while (rem >= NB - i) { rem -= NB - i; i++; }
    bi = i; bj = i + rem;
}

__device__ __forceinline__ void prefetch_tile(uint32_t dA, uint32_t dB, int bi, int bj, int tid) {
    const uint4* Ag = (const uint4*)(g_x8 + (size_t)bi * 128 * D);
    const uint4* Bg = (const uint4*)(g_x8 + (size_t)bj * 128 * D);
    #pragma unroll
    for (int it = 0; it < 4; it++) {
        int q = it * 256 + tid;             // 0..1023
        int row = q >> 3, seg = q & 7;
        uint32_t off = (uint32_t)row * ROWB + (uint32_t)seg * 16;
        cp16(dA + off, Ag + q);
        cp16(dB + off, Bg + q);
    }
}

__global__ __launch_bounds__(256, 2)
void k2_gram_mma(const float* __restrict__ x, const float* __restrict__ noise,
                 const float* __restrict__ phi, float* __restrict__ out,
                 float* __restrict__ out_scalar) {
    extern __shared__ __align__(16) unsigned char dsm[];
    __shared__ float rred[128 * 4];
    __shared__ float cred[128 * 2];
    __shared__ int   s_last, s_cnt;
    __shared__ float s_lse;

    uint32_t base = smem_u32(dsm);
    int tid = threadIdx.x;
    int wid = tid >> 5, lane = tid & 31;
    int warp_m = wid >> 2;          // 0..1  (64-row band)
    int warp_n = wid & 3;           // 0..3  (32-col band)
    int R0 = warp_m * 64;
    int C0 = warp_n * 32;
    int lr = lane >> 2;
    int lc = (lane & 3) * 2;

    uint32_t a_off = (uint32_t)(R0 + (lane & 15)) * ROWB + (uint32_t)((lane >> 4) * 16);
    uint32_t b_off = (uint32_t)(C0 + (lane & 7)) * ROWB + (uint32_t)(((lane >> 3) & 1) * 16);

    float var = softplus_var(phi);
    float half_inv = 0.5f / var;

    int ti = blockIdx.x;
    int bi = 0, bj = 0;
    bool active = (ti < NTILES);
    if (active) {
        decode_tile(ti, bi, bj);
        prefetch_tile(base, base + TILEB, bi, bj, tid);
        CP_COMMIT();
    }

    // ---- out = x + var*noise, grid-strided; hides under tile-0 load + tensor work ----
    for (int q = blockIdx.x * 256 + tid; q < N * D / 4; q += K2GRID * 256) {
        float4 xv = ((const float4*)x)[q];
        float4 nv = ((const float4*)noise)[q];
        float4 ov;
        ov.x = fmaf(var, nv.x, xv.x); ov.y = fmaf(var, nv.y, xv.y);
        ov.z = fmaf(var, nv.z, xv.z); ov.w = fmaf(var, nv.w, xv.w);
        ((float4*)out)[q] = ov;
    }

    int cur = 0;
    while (active) {
        int nti = ti + K2GRID;
        int nbi = 0, nbj = 0;
        bool have_next = (nti < NTILES);
        if (have_next) {
            decode_tile(nti, nbi, nbj);
            uint32_t nb = base + (cur ^ 1) * 2 * TILEB;
            prefetch_tile(nb, nb + TILEB, nbi, nbj, tid);
            CP_COMMIT();
        }

        float aq[4][2], bq[4][2];
        #pragma unroll
        for (int mt = 0; mt < 4; mt++) {
            aq[mt][0] = g_sq[bi * 128 + R0 + mt * 16 + lr];
            aq[mt][1] = g_sq[bi * 128 + R0 + mt * 16 + lr + 8];
        }
        #pragma unroll
        for (int nt = 0; nt < 4; nt++) {
            bq[nt][0] = g_sq[bj * 128 + C0 + nt * 8 + lc];
            bq[nt][1] = g_sq[bj * 128 + C0 + nt * 8 + lc + 1];
        }

        if (have_next) CP_WAIT1(); else CP_WAIT0();
        __syncthreads();

        uint32_t sa  = base + cur * 2 * TILEB;
        uint32_t sbm = sa + TILEB;
        bool diag = (bi == bj);

        uint32_t acc[4][4][2];
        #pragma unroll
        for (int mt = 0; mt < 4; mt++)
            #pragma unroll
            for (int nt = 0; nt < 4; nt++) { acc[mt][nt][0] = 0u; acc[mt][nt][1] = 0u; }

        #pragma unroll
        for (int kt = 0; kt < 4; kt++) {
            uint32_t kbase = (uint32_t)kt * 32;
            uint32_t af[4][4];
            #pragma unroll
            for (int mt = 0; mt < 4; mt++)
                ldsm_x4(af[mt][0], af[mt][1], af[mt][2], af[mt][3],
                        sa + a_off + (uint32_t)(mt * 16) * ROWB + kbase);
            uint32_t bf[4][2];
            #pragma unroll
            for (int nt = 0; nt < 4; nt++)
                ldsm_x2(bf[nt][0], bf[nt][1],
                        sbm + b_off + (uint32_t)(nt * 8) * ROWB + kbase);
            #pragma unroll
            for (int mt = 0; mt < 4; mt++)
                #pragma unroll
                for (int nt = 0; nt < 4; nt++)
                    mma_fp8_h(acc[mt][nt], af[mt], bf[nt]);
        }

        // ---- epilogue ----
        float rm[4][2], cm[4][2];
        #pragma unroll
        for (int i = 0; i < 4; i++) { rm[i][0] = rm[i][1] = NEGINF; cm[i][0] = cm[i][1] = NEGINF; }

        #pragma unroll
        for (int mt = 0; mt < 4; mt++) {
            int r0 = R0 + mt * 16 + lr;
            #pragma unroll
            for (int nt = 0; nt < 4; nt++) {
                int c0 = C0 + nt * 8 + lc;
                float2 lo = __half22float2(*(const __half2*)&acc[mt][nt][0]);
                float2 hi = __half22float2(*(const __half2*)&acc[mt][nt][1]);
                float av[4] = {lo.x, lo.y, hi.x, hi.y};
                #pragma unroll
                for (int rg = 0; rg < 4; rg++) {
                    int rr = r0 + (rg >> 1) * 8;
                    int cc = c0 + (rg & 1);
                    float a = av[rg];
                    float vr = fmaf(2.f, a, -bq[nt][rg & 1]);
                    float vc = fmaf(2.f, a, -aq[mt][rg >> 1]);
                    if (diag && rr == cc) { vr = NEGINF; vc = NEGINF; }
                    rm[mt][rg >> 1] = fmaxf(rm[mt][rg >> 1], vr);
                    cm[nt][rg & 1]  = fmaxf(cm[nt][rg & 1], vc);
                }
            }
        }

        #pragma unroll
        for (int mt = 0; mt < 4; mt++)
            #pragma unroll
            for (int h = 0; h < 2; h++) {
                float v = rm[mt][h];
                v = fmaxf(v, __shfl_xor_sync(0xffffffffu, v, 1));
                v = fmaxf(v, __shfl_xor_sync(0xffffffffu, v, 2));
                rm[mt][h] = v;
            }
        #pragma unroll
        for (int nt = 0; nt < 4; nt++)
            #pragma unroll
            for (int h = 0; h < 2; h++) {
                float v = cm[nt][h];
                v = fmaxf(v, __shfl_xor_sync(0xffffffffu, v, 4));
                v = fmaxf(v, __shfl_xor_sync(0xffffffffu, v, 8));
                v = fmaxf(v, __shfl_xor_sync(0xffffffffu, v, 16));
                cm[nt][h] = v;
            }

        if ((lane & 3) == 0) {
            #pragma unroll
            for (int mt = 0; mt < 4; mt++) {
                rred[(R0 + mt * 16 + lr) * 4 + warp_n]     = rm[mt][0];
                rred[(R0 + mt * 16 + lr + 8) * 4 + warp_n] = rm[mt][1];
            }
        }
        if (lane < 4) {
            #pragma unroll
            for (int nt = 0; nt < 4; nt++) {
                cred[(C0 + nt * 8 + lc) * 2 + warp_m]     = cm[nt][0];
                cred[(C0 + nt * 8 + lc + 1) * 2 + warp_m] = cm[nt][1];
            }
        }
        __syncthreads();
        if (tid < 128) {
            float m = fmaxf(fmaxf(rred[tid * 4 + 0], rred[tid * 4 + 1]),
                            fmaxf(rred[tid * 4 + 2], rred[tid * 4 + 3]));
            atomicMax(&g_rowmax[bi * 128 + tid], fenc(m));
        } else {
            int t = tid - 128;
            float m = fmaxf(cred[t * 2 + 0], cred[t * 2 + 1]);
            atomicMax(&g_rowmax[bj * 128 + t], fenc(m));
        }
        __syncthreads();

        if (!have_next) break;
        ti = nti; bi = nbi; bj = nbj; cur ^= 1;
    }

    // ---- completion ticket: last CTA runs the tail ----
    __syncthreads();
    if (tid == 0) {
        __threadfence();
        int t = atomicAdd(&g_ticket, 1);
        s_last = (t == K2GRID - 1);
        s_cnt = 0;
        s_lse = 0.f;
    }
    __syncthreads();
    if (!s_last) return;
    __threadfence();   // acquire: all rowmax atomics visible

    // screen all rows
    for (int i = tid; i < N; i += 256) {
        float m = fdec(g_rowmax[i]);
        float zmax = fminf((m - g_sq[i]) * half_inv, 0.f);
        if (zmax > -34.f) {
            int k = atomicAdd(&s_cnt, 1);
            g_flaglist[k] = i;
        }
    }
    __syncthreads();
    int nf = s_cnt;

    // exact fp32 fallback for flagged rows (expected: none)
    float* xi = rred;
    float* part = rred + 128;
    for (int f = 0; f < nf; f++) {
        int i = g_flaglist[f];
        if (tid < D) xi[tid] = x[(size_t)i * D + tid];
        __syncthreads();
        float sqi = g_sq[i];
        float s = 0.f;
        for (int j = tid; j < N; j += 256) {
            const float* xj = x + (size_t)j * D;
            float dot = 0.f;
            #pragma unroll 8
            for (int k = 0; k < D; k++) dot += xi[k] * xj[k];
            float d2 = fmaxf(sqi + g_sq[j] - 2.f * dot, 0.f);
            s += expf(-d2 * half_inv);
        }
        part[tid] = s;
        __syncthreads();
        for (int o = 128; o; o >>= 1) {
            if (tid < o) part[tid] += part[tid + o];
            __syncthreads();
        }
        if (tid == 0) s_lse += logf(part[0]);
        __syncthreads();
    }

    if (tid == 0) {
        float kde = s_lse / (float)N;   // screened rows contribute log(1) = 0
        float ixt = (logf((float)N) - kde) * 1.4426950408889634f;
        *out_scalar = ixt;
    }
}

// ---------------- launch ----------------
extern "C" void kernel_launch(void* const* d_in, const int* in_sizes, int n_in,
                              void* d_out, int out_size) {
    const float* x     = (const float*)d_in[0];
    const float* phi   = (const float*)d_in[1];
    const float* noise = (const float*)d_in[2];
    float* out = (float*)d_out;

    static bool attr_done = false;
    if (!attr_done) {
        cudaFuncSetAttribute(k2_gram_mma, cudaFuncAttributeMaxDynamicSharedMemorySize,
                             4 * TILEB);
        attr_done = true;
    }

    k1_lite<<<N / 16, 256>>>(x);
    k2_gram_mma<<<K2GRID, 256, 4 * TILEB>>>(x, noise, phi, out, out + out_size - 1);
}

// round 11
// speedup vs baseline: 1.2056x; 1.2056x over previous
#include <cuda_runtime.h>
#include <cuda_bf16.h>
#include <cuda_fp16.h>
#include <cuda_fp8.h>
#include <math.h>
#include <stdint.h>

#define N 8192
#define D 128
#define NB 64                 // N / 128
#define NTILES (NB * (NB + 1) / 2)     // 2080
#define ENC_NEGINF 0x007FFFFFu
#define NEGINF __int_as_float(0xff800000)

// ---------------- scratch (static __device__, no allocation) ----------------
__device__ unsigned g_rowmax[N];   // encoded-float max_{j!=i} (2*G_ij - sq_j)
__device__ float    g_sq[N];
__device__ int      g_flaglist[N];
__device__ __align__(16) unsigned char g_x8[N * D];   // fp8 e4m3 copy of x (1 MB)

// ---------------- helpers ----------------
__device__ __forceinline__ uint32_t smem_u32(const void* p) {
    uint32_t a;
    asm("{ .reg .u64 t; cvta.to.shared.u64 t, %1; cvt.u32.u64 %0, t; }" : "=r"(a) : "l"(p));
    return a;
}
__device__ __forceinline__ float softplus_var(const float* __restrict__ phi) {
    float p = *phi;
    return (p > 20.f) ? p : log1pf(expf(p));
}
// order-preserving float<->uint encoding for atomicMax
__device__ __forceinline__ unsigned fenc(float f) {
    unsigned u = __float_as_uint(f);
    return (u & 0x80000000u) ? ~u : (u | 0x80000000u);
}
__device__ __forceinline__ float fdec(unsigned e) {
    return (e & 0x80000000u) ? __uint_as_float(e & 0x7FFFFFFFu)
                             : __uint_as_float(~e);
}

__device__ __forceinline__ void ldsm_x4(uint32_t& r0, uint32_t& r1, uint32_t& r2, uint32_t& r3,
                                        uint32_t addr) {
    asm volatile("ldmatrix.sync.aligned.m8n8.x4.shared.b16 {%0,%1,%2,%3}, [%4];"
                 : "=r"(r0), "=r"(r1), "=r"(r2), "=r"(r3) : "r"(addr));
}
__device__ __forceinline__ void ldsm_x2(uint32_t& r0, uint32_t& r1, uint32_t addr) {
    asm volatile("ldmatrix.sync.aligned.m8n8.x2.shared.b16 {%0,%1}, [%2];"
                 : "=r"(r0), "=r"(r1) : "r"(addr));
}
// fp8 e4m3 mma with f16 accumulators
__device__ __forceinline__ void mma_fp8_h(uint32_t* d, const uint32_t* a, const uint32_t* b) {
    asm volatile(
        "mma.sync.aligned.m16n8k32.row.col.f16.e4m3.e4m3.f16 "
        "{%0,%1}, {%2,%3,%4,%5}, {%6,%7}, {%0,%1};"
        : "+r"(d[0]), "+r"(d[1])
        : "r"(a[0]), "r"(a[1]), "r"(a[2]), "r"(a[3]), "r"(b[0]), "r"(b[1]));
}
__device__ __forceinline__ uint16_t cvt2_e4m3(float hi, float lo) {
    uint16_t r;
    asm("cvt.rn.satfinite.e4m3x2.f32 %0, %1, %2;" : "=h"(r) : "f"(hi), "f"(lo));
    return r;
}

// ---------------- k_out: out = x + var*noise (overlapped on second stream) ----------------
__global__ __launch_bounds__(256) void k_out(const float* __restrict__ x,
                                             const float* __restrict__ phi,
                                             const float* __restrict__ noise,
                                             float* __restrict__ out) {
    int q = blockIdx.x * 256 + threadIdx.x;    // 1024 CTAs -> exactly N*D/4
    float var = softplus_var(phi);
    float4 xv = ((const float4*)x)[q];
    float4 nv = ((const float4*)noise)[q];
    float4 ov;
    ov.x = fmaf(var, nv.x, xv.x); ov.y = fmaf(var, nv.y, xv.y);
    ov.z = fmaf(var, nv.z, xv.z); ov.w = fmaf(var, nv.w, xv.w);
    ((float4*)out)[q] = ov;
}

// ---------------- K1 lite: g_x8 + g_sq + rowmax init only ----------------
__global__ __launch_bounds__(256) void k1_lite(const float* __restrict__ x) {
    int tid = threadIdx.x;
    int gw = blockIdx.x * 8 + (tid >> 5);     // 4096 warps, 2 rows each
    int lane = tid & 31;
    int r0 = gw * 2;

    float4 xs[2];
    #pragma unroll
    for (int rr = 0; rr < 2; rr++) xs[rr] = ((const float4*)x)[(r0 + rr) * 32 + lane];

    #pragma unroll
    for (int rr = 0; rr < 2; rr++) {
        float4 xv = xs[rr];
        uint32_t packed = (uint32_t)cvt2_e4m3(xv.y, xv.x)
                        | ((uint32_t)cvt2_e4m3(xv.w, xv.z) << 16);
        ((uint32_t*)g_x8)[(r0 + rr) * 32 + lane] = packed;

        float s = xv.x * xv.x + xv.y * xv.y + xv.z * xv.z + xv.w * xv.w;
        #pragma unroll
        for (int o = 16; o; o >>= 1) s += __shfl_xor_sync(0xffffffffu, s, o);
        if (lane == 0) g_sq[r0 + rr] = s;
    }
    if (lane < 2) g_rowmax[r0 + lane] = ENC_NEGINF;
}

// ---------------- K2: fp8 mma.sync Gram (f16 accum) — round-8 config, UNTOUCHED ----------------
#define ROWB 144

__global__ __launch_bounds__(256, 2)
void k2_gram_mma() {
    __shared__ __align__(16) unsigned char smA[128 * ROWB];
    __shared__ __align__(16) unsigned char smB[128 * ROWB];
    __shared__ float asq[128], bsq[128];
    __shared__ float rred[128 * 4];
    __shared__ float cred[128 * 2];

    uint32_t sa = smem_u32(smA);
    uint32_t sbm = smem_u32(smB);
    int tid = threadIdx.x;
    int wid = tid >> 5, lane = tid & 31;
    int warp_m = wid >> 2;          // 0..1  (64-row band)
    int warp_n = wid & 3;           // 0..3  (32-col band)

    // triangular block decode: b -> (bi, bj), bi <= bj
    int b = blockIdx.x;
    int bi = 0, rem = b;
    while (rem >= NB - bi) { rem -= NB - bi; bi++; }
    int bj = bi + rem;
    bool diag = (bi == bj);

    // ---- load tiles (fp8, 128 B per row = 8 uint4) ----
    const uint4* Ag = (const uint4*)(g_x8 + (size_t)bi * 128 * D);
    const uint4* Bg = (const uint4*)(g_x8 + (size_t)bj * 128 * D);
    #pragma unroll
    for (int it = 0; it < 4; it++) {
        int q = it * 256 + tid;             // 0..1023
        int row = q >> 3, seg = q & 7;
        uint32_t off = (uint32_t)row * ROWB + (uint32_t)seg * 16;
        *(uint4*)(smA + off) = Ag[q];
        *(uint4*)(smB + off) = Bg[q];
    }
    if (tid < 128) asq[tid] = g_sq[bi * 128 + tid];
    else           bsq[tid - 128] = g_sq[bj * 128 + tid - 128];
    __syncthreads();

    // ---- mma mainloop: warp tile 64x32, K=128 (4 k-steps of 32) ----
    int R0 = warp_m * 64;
    int C0 = warp_n * 32;
    uint32_t acc[4][4][2];
    #pragma unroll
    for (int mt = 0; mt < 4; mt++)
        #pragma unroll
        for (int nt = 0; nt < 4; nt++) { acc[mt][nt][0] = 0u; acc[mt][nt][1] = 0u; }

    uint32_t a_row = (uint32_t)(R0 + (lane & 15));
    uint32_t a_kb  = (uint32_t)((lane >> 4) * 16);
    uint32_t b_row = (uint32_t)(C0 + (lane & 7));
    uint32_t b_kb  = (uint32_t)(((lane >> 3) & 1) * 16);

    #pragma unroll
    for (int kt = 0; kt < 4; kt++) {
        uint32_t kbase = (uint32_t)kt * 32;   // 32 fp8 bytes per k-step
        uint32_t af[4][4];
        #pragma unroll
        for (int mt = 0; mt < 4; mt++) {
            uint32_t addr = sa + (a_row + mt * 16) * ROWB + kbase + a_kb;
            ldsm_x4(af[mt][0], af[mt][1], af[mt][2], af[mt][3], addr);
        }
        uint32_t bf[4][2];
        #pragma unroll
        for (int nt = 0; nt < 4; nt++) {
            uint32_t addr = sbm + (b_row + nt * 8) * ROWB + kbase + b_kb;
            ldsm_x2(bf[nt][0], bf[nt][1], addr);
        }
        #pragma unroll
        for (int mt = 0; mt < 4; mt++)
            #pragma unroll
            for (int nt = 0; nt < 4; nt++)
                mma_fp8_h(acc[mt][nt], af[mt], bf[nt]);
    }

    // ---- epilogue: fragment rows = lane>>2 (+8), cols = 2*(lane&3) (+1) ----
    int lr = lane >> 2;
    int lc = (lane & 3) * 2;

    float aq[4][2], bq[4][2];
    #pragma unroll
    for (int mt = 0; mt < 4; mt++) {
        aq[mt][0] = asq[R0 + mt * 16 + lr];
        aq[mt][1] = asq[R0 + mt * 16 + lr + 8];
    }
    #pragma unroll
    for (int nt = 0; nt < 4; nt++) {
        bq[nt][0] = bsq[C0 + nt * 8 + lc];
        bq[nt][1] = bsq[C0 + nt * 8 + lc + 1];
    }

    float rm[4][2], cm[4][2];
    #pragma unroll
    for (int i = 0; i < 4; i++) { rm[i][0] = rm[i][1] = NEGINF; cm[i][0] = cm[i][1] = NEGINF; }

    #pragma unroll
    for (int mt = 0; mt < 4; mt++) {
        int r0 = R0 + mt * 16 + lr;
        #pragma unroll
        for (int nt = 0; nt < 4; nt++) {
            int c0 = C0 + nt * 8 + lc;
            float2 lo = __half22float2(*(const __half2*)&acc[mt][nt][0]);
            float2 hi = __half22float2(*(const __half2*)&acc[mt][nt][1]);
            float av[4] = {lo.x, lo.y, hi.x, hi.y};
            #pragma unroll
            for (int rg = 0; rg < 4; rg++) {
                int rr = r0 + (rg >> 1) * 8;
                int cc = c0 + (rg & 1);
                float a = av[rg];
                float vr = fmaf(2.f, a, -bq[nt][rg & 1]);
                float vc = fmaf(2.f, a, -aq[mt][rg >> 1]);
                if (diag && rr == cc) { vr = NEGINF; vc = NEGINF; }
                rm[mt][rg >> 1] = fmaxf(rm[mt][rg >> 1], vr);
                cm[nt][rg & 1]  = fmaxf(cm[nt][rg & 1], vc);
            }
        }
    }

    #pragma unroll
    for (int mt = 0; mt < 4; mt++)
        #pragma unroll
        for (int h = 0; h < 2; h++) {
            float v = rm[mt][h];
            v = fmaxf(v, __shfl_xor_sync(0xffffffffu, v, 1));
            v = fmaxf(v, __shfl_xor_sync(0xffffffffu, v, 2));
            rm[mt][h] = v;
        }
    #pragma unroll
    for (int nt = 0; nt < 4; nt++)
        #pragma unroll
        for (int h = 0; h < 2; h++) {
            float v = cm[nt][h];
            v = fmaxf(v, __shfl_xor_sync(0xffffffffu, v, 4));
            v = fmaxf(v, __shfl_xor_sync(0xffffffffu, v, 8));
            v = fmaxf(v, __shfl_xor_sync(0xffffffffu, v, 16));
            cm[nt][h] = v;
        }

    if ((lane & 3) == 0) {
        #pragma unroll
        for (int mt = 0; mt < 4; mt++) {
            rred[(R0 + mt * 16 + lr) * 4 + warp_n]     = rm[mt][0];
            rred[(R0 + mt * 16 + lr + 8) * 4 + warp_n] = rm[mt][1];
        }
    }
    if (lane < 4) {
        #pragma unroll
        for (int nt = 0; nt < 4; nt++) {
            cred[(C0 + nt * 8 + lc) * 2 + warp_m]     = cm[nt][0];
            cred[(C0 + nt * 8 + lc + 1) * 2 + warp_m] = cm[nt][1];
        }
    }
    __syncthreads();
    if (tid < 128) {
        float m = fmaxf(fmaxf(rred[tid * 4 + 0], rred[tid * 4 + 1]),
                        fmaxf(rred[tid * 4 + 2], rred[tid * 4 + 3]));
        atomicMax(&g_rowmax[bi * 128 + tid], fenc(m));
    } else {
        int t = tid - 128;
        float m = fmaxf(cred[t * 2 + 0], cred[t * 2 + 1]);
        atomicMax(&g_rowmax[bj * 128 + t], fenc(m));
    }
}

// ---------------- K3: single-CTA tail: screen -> exact fallback -> reduce ----------------
__global__ __launch_bounds__(1024) void k3_tail(const float* __restrict__ x,
                                                const float* __restrict__ phi,
                                                float* __restrict__ out_scalar) {
    __shared__ float xi[D];
    __shared__ float part[1024];
    __shared__ int   s_cnt;
    __shared__ float s_lse;
    int tid = threadIdx.x;
    float var = softplus_var(phi);
    float half_inv = 0.5f / var;

    if (tid == 0) { s_cnt = 0; s_lse = 0.f; }
    __syncthreads();

    #pragma unroll
    for (int it = 0; it < 8; it++) {
        int i = it * 1024 + tid;
        float m = fdec(g_rowmax[i]);
        float zmax = fminf((m - g_sq[i]) * half_inv, 0.f);
        if (zmax > -34.f) {
            int k = atomicAdd(&s_cnt, 1);
            g_flaglist[k] = i;
        }
    }
    __syncthreads();
    int nf = s_cnt;

    for (int f = 0; f < nf; f++) {
        int i = g_flaglist[f];
        if (tid < D) xi[tid] = x[(size_t)i * D + tid];
        __syncthreads();
        float sqi = g_sq[i];
        float s = 0.f;
        for (int j = tid; j < N; j += 1024) {
            const float* xj = x + (size_t)j * D;
            float dot = 0.f;
            #pragma unroll 8
            for (int k = 0; k < D; k++) dot += xi[k] * xj[k];
            float d2 = fmaxf(sqi + g_sq[j] - 2.f * dot, 0.f);
            s += expf(-d2 * half_inv);
        }
        part[tid] = s;
        __syncthreads();
        for (int o = 512; o; o >>= 1) {
            if (tid < o) part[tid] += part[tid + o];
            __syncthreads();
        }
        if (tid == 0) s_lse += logf(part[0]);
        __syncthreads();
    }

    if (tid == 0) {
        float kde = s_lse / (float)N;   // screened rows contribute log(1) = 0
        float ixt = (logf((float)N) - kde) * 1.4426950408889634f;
        *out_scalar = ixt;
    }
}

// ---------------- launch: fork k_out onto a second stream ----------------
extern "C" void kernel_launch(void* const* d_in, const int* in_sizes, int n_in,
                              void* d_out, int out_size) {
    const float* x     = (const float*)d_in[0];
    const float* phi   = (const float*)d_in[1];
    const float* noise = (const float*)d_in[2];
    float* out = (float*)d_out;

    static cudaStream_t s2 = nullptr;
    static cudaEvent_t evF = nullptr, evJ = nullptr;
    if (s2 == nullptr) {   // first call is the uncaptured correctness run
        cudaStreamCreateWithFlags(&s2, cudaStreamNonBlocking);
        cudaEventCreateWithFlags(&evF, cudaEventDisableTiming);
        cudaEventCreateWithFlags(&evJ, cudaEventDisableTiming);
    }

    // fork: out-computation runs concurrently with k1_lite + k2
    cudaEventRecord(evF, 0);
    cudaStreamWaitEvent(s2, evF, 0);
    k_out<<<N * D / 4 / 256, 256, 0, s2>>>(x, phi, noise, out);
    cudaEventRecord(evJ, s2);

    // main chain
    k1_lite<<<N / 16, 256>>>(x);
    k2_gram_mma<<<NTILES, 256>>>();
    k3_tail<<<1, 1024>>>(x, phi, out + out_size - 1);

    // join
    cudaStreamWaitEvent(0, evJ, 0);
}